// round 6
// baseline (speedup 1.0000x reference)
#include <cuda_runtime.h>
#include <cstdint>

// Unfold (im2col) — SMEM-staged 16-row tiles + big TMA bulk stores.
// x: [16, 64, 112, 112] f32 ; out: [16, 576, 112, 112] f32
// out[n, c*9 + kh*3 + kw, h, w] = x[n, c, h+kh-1, w+kw-1] (0 outside)
//
// Block = (n, c, 16-row band), 256 threads. Warp w owns rows h0+2w,h0+2w+1:
// loads 4 aligned float4 rows, builds 9 shifted variants via shfl, stores to
// SMEM. Then 9 cp.async.bulk chunks of 7168B each (56 full 128B lines,
// line-aligned) stream the tile to GMEM.

#define HWDIM 112
#define PLANE (HWDIM * HWDIM)   // 12544
#define ROWS  16
#define BANDS (HWDIM / ROWS)    // 7
#define CHUNK_BYTES (ROWS * HWDIM * 4)   // 7168

__global__ __launch_bounds__(256) void unfold_kernel(
    const float* __restrict__ x, float* __restrict__ out)
{
    __shared__ __align__(16) float sm[9][ROWS][HWDIM];   // 63 KB

    const int blk = blockIdx.x;
    const int hb  = blk % BANDS;
    const int nc  = blk / BANDS;            // n*64 + c
    const int h0  = hb * ROWS;

    const int wid  = threadIdx.x >> 5;      // 0..7
    const int lane = threadIdx.x & 31;
    const int hr   = wid * 2;               // local row pair base
    const int h    = h0 + hr;

    const bool wok = lane < 28;
    const int w0 = lane * 4;

    const float* plane = x + (int64_t)nc * PLANE;

    // input rows h-1 .. h+2
    float4 r[4];
#pragma unroll
    for (int i = 0; i < 4; ++i) {
        const int ih = h - 1 + i;
        if (wok && (unsigned)ih < HWDIM)
            r[i] = *reinterpret_cast<const float4*>(plane + ih * HWDIM + w0);
        else
            r[i] = make_float4(0.f, 0.f, 0.f, 0.f);
    }

    float4 vm[4], vp[4];
#pragma unroll
    for (int i = 0; i < 4; ++i) {
        float pw = __shfl_up_sync(0xFFFFFFFFu, r[i].w, 1);
        if (lane == 0) pw = 0.f;                              // left pad
        float nx = __shfl_down_sync(0xFFFFFFFFu, r[i].x, 1);  // lane27 -> 0
        vm[i] = make_float4(pw, r[i].x, r[i].y, r[i].z);      // kw = -1
        vp[i] = make_float4(r[i].y, r[i].z, r[i].w, nx);      // kw = +1
    }

    if (wok) {
#pragma unroll
        for (int j = 0; j < 2; ++j) {            // local row hr+j
#pragma unroll
            for (int i = 0; i < 3; ++i) {        // kh = i-1 -> reg idx i+j
                *reinterpret_cast<float4*>(&sm[i * 3 + 0][hr + j][w0]) = vm[i + j];
                *reinterpret_cast<float4*>(&sm[i * 3 + 1][hr + j][w0]) = r[i + j];
                *reinterpret_cast<float4*>(&sm[i * 3 + 2][hr + j][w0]) = vp[i + j];
            }
        }
    }

    __syncthreads();
    asm volatile("fence.proxy.async.shared::cta;" ::: "memory");

    // 9 bulk stores, one per kk-plane chunk (7168B contiguous, line-aligned)
    if (threadIdx.x < 9) {
        const int kk = threadIdx.x;
        uint32_t saddr;
        asm("{ .reg .u64 t; cvta.to.shared.u64 t, %1; cvt.u32.u64 %0, t; }"
            : "=r"(saddr) : "l"(&sm[kk][0][0]));
        float* gdst = out + ((int64_t)(nc * 9 + kk) * HWDIM + h0) * HWDIM;
        asm volatile(
            "cp.async.bulk.global.shared::cta.bulk_group [%0], [%1], %2;"
            :: "l"(gdst), "r"(saddr), "n"(CHUNK_BYTES) : "memory");
        asm volatile("cp.async.bulk.commit_group;" ::: "memory");
        asm volatile("cp.async.bulk.wait_group 0;" ::: "memory");
    }
}

extern "C" void kernel_launch(void* const* d_in, const int* in_sizes, int n_in,
                              void* d_out, int out_size)
{
    const float* x = (const float*)d_in[0];
    float* out = (float*)d_out;

    const int blocks = 16 * 64 * BANDS;   // 7168
    unfold_kernel<<<blocks, 256>>>(x, out);
}

// round 7
// speedup vs baseline: 1.0112x; 1.0112x over previous
#include <cuda_runtime.h>
#include <cstdint>

// Unfold (im2col) — SMEM-staged 8-row tiles + TMA bulk stores,
// with TMA issue spread across all 8 warps.
// x: [16, 64, 112, 112] f32 ; out: [16, 576, 112, 112] f32
// out[n, c*9 + kh*3 + kw, h, w] = x[n, c, h+kh-1, w+kw-1] (0 outside)

#define HWDIM 112
#define PLANE (HWDIM * HWDIM)   // 12544
#define ROWS  8
#define BANDS (HWDIM / ROWS)    // 14
#define CHUNK_BYTES (ROWS * HWDIM * 4)   // 3584 = 28 x 128B lines

__global__ __launch_bounds__(256) void unfold_kernel(
    const float* __restrict__ x, float* __restrict__ out)
{
    __shared__ __align__(16) float sm[9][ROWS][HWDIM];   // 31.5 KB

    const int blk = blockIdx.x;
    const int hb  = blk % BANDS;
    const int nc  = blk / BANDS;            // n*64 + c
    const int h0  = hb * ROWS;

    const int wid  = threadIdx.x >> 5;      // 0..7 -> row h0+wid
    const int lane = threadIdx.x & 31;
    const int h    = h0 + wid;

    const bool wok = lane < 28;
    const int w0 = lane * 4;

    const float* plane = x + (int64_t)nc * PLANE;

    float4 r[3];
#pragma unroll
    for (int i = 0; i < 3; ++i) {
        const int ih = h - 1 + i;
        if (wok && (unsigned)ih < HWDIM)
            r[i] = *reinterpret_cast<const float4*>(plane + ih * HWDIM + w0);
        else
            r[i] = make_float4(0.f, 0.f, 0.f, 0.f);
    }

#pragma unroll
    for (int i = 0; i < 3; ++i) {
        float pw = __shfl_up_sync(0xFFFFFFFFu, r[i].w, 1);
        if (lane == 0) pw = 0.f;                               // left pad
        float nx = __shfl_down_sync(0xFFFFFFFFu, r[i].x, 1);   // lane27 -> 0
        if (wok) {
            *reinterpret_cast<float4*>(&sm[i * 3 + 0][wid][w0]) =
                make_float4(pw, r[i].x, r[i].y, r[i].z);        // kw = -1
            *reinterpret_cast<float4*>(&sm[i * 3 + 1][wid][w0]) = r[i];
            *reinterpret_cast<float4*>(&sm[i * 3 + 2][wid][w0]) =
                make_float4(r[i].y, r[i].z, r[i].w, nx);        // kw = +1
        }
    }

    __syncthreads();
    asm volatile("fence.proxy.async.shared::cta;" ::: "memory");

    // Spread the 9 bulk stores across warps: warp k issues plane k,
    // warp 0 additionally issues plane 8. Commit per issuing thread,
    // wait only at the end.
    if (lane == 0) {
        const int nplanes = (wid == 0) ? 2 : 1;
#pragma unroll
        for (int q = 0; q < 2; ++q) {
            if (q < nplanes) {
                const int kk = (q == 0) ? wid : 8;
                uint32_t saddr;
                asm("{ .reg .u64 t; cvta.to.shared.u64 t, %1; cvt.u32.u64 %0, t; }"
                    : "=r"(saddr) : "l"(&sm[kk][0][0]));
                float* gdst = out + ((int64_t)(nc * 9 + kk) * HWDIM + h0) * HWDIM;
                asm volatile(
                    "cp.async.bulk.global.shared::cta.bulk_group [%0], [%1], %2;"
                    :: "l"(gdst), "r"(saddr), "n"(CHUNK_BYTES) : "memory");
            }
        }
        asm volatile("cp.async.bulk.commit_group;" ::: "memory");
        asm volatile("cp.async.bulk.wait_group 0;" ::: "memory");
    }
}

extern "C" void kernel_launch(void* const* d_in, const int* in_sizes, int n_in,
                              void* d_out, int out_size)
{
    const float* x = (const float*)d_in[0];
    float* out = (float*)d_out;

    const int blocks = 16 * 64 * BANDS;   // 14336
    unfold_kernel<<<blocks, 256>>>(x, out);
}